// round 2
// baseline (speedup 1.0000x reference)
#include <cuda_runtime.h>

#define NMAX 100000
#define F1 32   // heads1 * ch1 = 2*16

// ---------- scratch (device globals; no allocations allowed) ----------
__device__ __align__(16) float g_h1  [NMAX * F1];  // layer1 features per node
__device__ __align__(16) float g_als1[NMAX * 2];
__device__ __align__(16) float g_ald1[NMAX * 2];
__device__ __align__(16) float g_s1  [NMAX * 2];   // segment exp-sums
__device__ __align__(16) float g_acc1[NMAX * F1];  // segment msg accumulators
__device__ __align__(16) float g_h2  [NMAX * 2];
__device__ __align__(16) float g_als2[NMAX];
__device__ __align__(16) float g_ald2[NMAX];
__device__ __align__(16) float g_s2  [NMAX];
__device__ __align__(16) float g_acc2[NMAX * 2];

// ---------- vector reductions (fire-and-forget REDG) ----------
__device__ __forceinline__ void red4(float* p, float a, float b, float c, float d) {
    asm volatile("red.global.add.v4.f32 [%0], {%1,%2,%3,%4};"
                 :: "l"(__cvta_generic_to_global(p)), "f"(a), "f"(b), "f"(c), "f"(d)
                 : "memory");
}
__device__ __forceinline__ void red2(float* p, float a, float b) {
    asm volatile("red.global.add.v2.f32 [%0], {%1,%2};"
                 :: "l"(__cvta_generic_to_global(p)), "f"(a), "f"(b)
                 : "memory");
}
__device__ __forceinline__ void red1(float* p, float a) {
    asm volatile("red.global.add.f32 [%0], %1;"
                 :: "l"(__cvta_generic_to_global(p)), "f"(a)
                 : "memory");
}

// ---------- K1: layer-1 node transform + logits + accumulator init ----------
__global__ void k_node1(const float4* __restrict__ x,
                        const float*  __restrict__ W1,
                        const float*  __restrict__ a_src,
                        const float*  __restrict__ a_dst,
                        int N) {
    int n = blockIdx.x * blockDim.x + threadIdx.x;
    if (n >= N) return;
    float4 xv = x[n];
    float als0 = 0.f, als1 = 0.f, ald0 = 0.f, ald1 = 0.f;
    float* hp = &g_h1[(size_t)n * F1];
    float* ap = &g_acc1[(size_t)n * F1];
#pragma unroll
    for (int j = 0; j < F1; j++) {
        float h = xv.x * __ldg(&W1[j])
                + xv.y * __ldg(&W1[32 + j])
                + xv.z * __ldg(&W1[64 + j])
                + xv.w * __ldg(&W1[96 + j]);
        hp[j] = h;
        ap[j] = 0.f;
        float as = __ldg(&a_src[j]);   // a_src1 is [2,16] row-major: index j == h*16+c
        float ad = __ldg(&a_dst[j]);
        if (j < 16) { als0 += h * as; ald0 += h * ad; }
        else        { als1 += h * as; ald1 += h * ad; }
    }
    g_als1[n * 2]     = als0;  g_als1[n * 2 + 1] = als1;
    g_ald1[n * 2]     = ald0;  g_ald1[n * 2 + 1] = ald1;
    g_s1[n * 2]       = 0.f;   g_s1[n * 2 + 1]   = 0.f;
}

// ---------- K2: layer-1 edge pass (exp + scatter-add) ----------
__global__ void k_edge1(const int* __restrict__ ei, int E, int ET) {
    int e = blockIdx.x * blockDim.x + threadIdx.x;
    if (e >= ET) return;
    int s, d;
    if (e < E) { s = __ldg(&ei[e]); d = __ldg(&ei[E + e]); }
    else       { s = d = e - E; }   // appended self-loops

    float2 as = *(const float2*)&g_als1[s * 2];
    float2 ad = *(const float2*)&g_ald1[d * 2];
    float e0 = as.x + ad.x; e0 = (e0 > 0.f) ? e0 : 0.2f * e0;
    float e1 = as.y + ad.y; e1 = (e1 > 0.f) ? e1 : 0.2f * e1;
    float ex0 = __expf(e0);
    float ex1 = __expf(e1);

    red2(&g_s1[d * 2], ex0, ex1);

    const float4* hs = (const float4*)&g_h1[(size_t)s * F1];
    float* acc = &g_acc1[(size_t)d * F1];
#pragma unroll
    for (int q = 0; q < 8; q++) {
        float4 hv = hs[q];
        float sc = (q < 4) ? ex0 : ex1;
        red4(&acc[q * 4], hv.x * sc, hv.y * sc, hv.z * sc, hv.w * sc);
    }
}

// ---------- K3: finalize layer-1 (divide + bias + ELU), layer-2 node transform ----------
__global__ void k_node2(const float* __restrict__ b1,
                        const float* __restrict__ W2,
                        const float* __restrict__ a_src2,
                        const float* __restrict__ a_dst2,
                        int N) {
    int n = blockIdx.x * blockDim.x + threadIdx.x;
    if (n >= N) return;
    float inv0 = 1.f / g_s1[n * 2];
    float inv1 = 1.f / g_s1[n * 2 + 1];
    float h2a = 0.f, h2b = 0.f;
    const float* ap = &g_acc1[(size_t)n * F1];
#pragma unroll
    for (int j = 0; j < F1; j++) {
        float o = ap[j] * ((j < 16) ? inv0 : inv1) + __ldg(&b1[j]);
        o = (o > 0.f) ? o : expm1f(o);         // ELU (alpha=1)
        h2a += o * __ldg(&W2[j * 2]);
        h2b += o * __ldg(&W2[j * 2 + 1]);
    }
    g_h2[n * 2]     = h2a;
    g_h2[n * 2 + 1] = h2b;
    g_als2[n] = h2a * __ldg(&a_src2[0]) + h2b * __ldg(&a_src2[1]);
    g_ald2[n] = h2a * __ldg(&a_dst2[0]) + h2b * __ldg(&a_dst2[1]);
    g_s2[n] = 0.f;
    g_acc2[n * 2] = 0.f;
    g_acc2[n * 2 + 1] = 0.f;
}

// ---------- K4: layer-2 edge pass ----------
__global__ void k_edge2(const int* __restrict__ ei, int E, int ET) {
    int e = blockIdx.x * blockDim.x + threadIdx.x;
    if (e >= ET) return;
    int s, d;
    if (e < E) { s = __ldg(&ei[e]); d = __ldg(&ei[E + e]); }
    else       { s = d = e - E; }

    float v = g_als2[s] + g_ald2[d];
    v = (v > 0.f) ? v : 0.2f * v;
    float ex = __expf(v);

    red1(&g_s2[d], ex);
    float2 h = *(const float2*)&g_h2[s * 2];
    red2(&g_acc2[d * 2], ex * h.x, ex * h.y);
}

// ---------- K5: output ----------
__global__ void k_out(const float* __restrict__ b2, float* __restrict__ out, int N) {
    int n = blockIdx.x * blockDim.x + threadIdx.x;
    if (n >= N) return;
    float inv = 1.f / g_s2[n];
    out[n * 2]     = g_acc2[n * 2]     * inv + __ldg(&b2[0]);
    out[n * 2 + 1] = g_acc2[n * 2 + 1] * inv + __ldg(&b2[1]);
}

extern "C" void kernel_launch(void* const* d_in, const int* in_sizes, int n_in,
                              void* d_out, int out_size) {
    const float* x   = (const float*)d_in[0];
    const int*   ei  = (const int*)d_in[1];   // JAX default x64-disabled: int32
    const float* W1  = (const float*)d_in[2];
    const float* as1 = (const float*)d_in[3];
    const float* ad1 = (const float*)d_in[4];
    const float* b1  = (const float*)d_in[5];
    const float* W2  = (const float*)d_in[6];
    const float* as2 = (const float*)d_in[7];
    const float* ad2 = (const float*)d_in[8];
    const float* b2  = (const float*)d_in[9];
    float* out = (float*)d_out;

    int N  = in_sizes[0] / 4;   // x is [N,4]
    int E  = in_sizes[1] / 2;   // edge_index is [2,E]
    int ET = E + N;             // + self-loops

    const int TB = 256;
    k_node1<<<(N  + TB - 1) / TB, TB>>>((const float4*)x, W1, as1, ad1, N);
    k_edge1<<<(ET + TB - 1) / TB, TB>>>(ei, E, ET);
    k_node2<<<(N  + TB - 1) / TB, TB>>>(b1, W2, as2, ad2, N);
    k_edge2<<<(ET + TB - 1) / TB, TB>>>(ei, E, ET);
    k_out  <<<(N  + TB - 1) / TB, TB>>>(b2, out, N);
}

// round 3
// speedup vs baseline: 1.5382x; 1.5382x over previous
#include <cuda_runtime.h>

#define NMAX 100000
#define EMAX 1700000
#define F1 32            // heads1 * ch1 = 2*16
#define SCAN_B 1024
#define NBLKMAX ((NMAX + SCAN_B - 1) / SCAN_B)   // 98

// ---------- scratch ----------
__device__ __align__(16) float g_h1  [NMAX * F1];
__device__ __align__(16) float g_als1[NMAX * 2];
__device__ __align__(16) float g_ald1[NMAX * 2];
__device__ __align__(16) float g_h2  [NMAX * 2];
__device__ __align__(16) float g_als2[NMAX];
__device__ __align__(16) float g_ald2[NMAX];
__device__ int g_cnt [NMAX];        // per-dst degree (starts at 1 for self-loop)
__device__ int g_row [NMAX + 1];    // CSR row starts
__device__ int g_woff[NMAX];        // running write offsets for scatter
__device__ int g_aux [NBLKMAX];     // per-block scan sums
__device__ int g_src [EMAX];        // dst-sorted src ids

// ---------- K1: layer-1 node transform + logits; init degree=1 (self loop) ----------
__global__ void k_node1(const float4* __restrict__ x,
                        const float*  __restrict__ W1,
                        const float*  __restrict__ a_src,
                        const float*  __restrict__ a_dst,
                        int N) {
    int n = blockIdx.x * blockDim.x + threadIdx.x;
    if (n >= N) return;
    float4 xv = x[n];
    float als0 = 0.f, als1 = 0.f, ald0 = 0.f, ald1 = 0.f;
    float* hp = &g_h1[(size_t)n * F1];
#pragma unroll
    for (int j = 0; j < F1; j++) {
        float h = xv.x * __ldg(&W1[j])
                + xv.y * __ldg(&W1[32 + j])
                + xv.z * __ldg(&W1[64 + j])
                + xv.w * __ldg(&W1[96 + j]);
        hp[j] = h;
        float as = __ldg(&a_src[j]);
        float ad = __ldg(&a_dst[j]);
        if (j < 16) { als0 += h * as; ald0 += h * ad; }
        else        { als1 += h * as; ald1 += h * ad; }
    }
    g_als1[n * 2]     = als0;  g_als1[n * 2 + 1] = als1;
    g_ald1[n * 2]     = ald0;  g_ald1[n * 2 + 1] = ald1;
    g_cnt[n] = 1;   // self-loop pre-counted
}

// ---------- K2: histogram of dst over the E real edges ----------
__global__ void k_hist(const int* __restrict__ ei, int E) {
    int e = blockIdx.x * blockDim.x + threadIdx.x;
    if (e >= E) return;
    atomicAdd(&g_cnt[__ldg(&ei[E + e])], 1);
}

// ---------- K3a: per-block exclusive scan of counts ----------
__global__ void k_scanA(int N) {
    __shared__ int sm[SCAN_B];
    int t = threadIdx.x;
    int i = blockIdx.x * SCAN_B + t;
    int c = (i < N) ? g_cnt[i] : 0;
    sm[t] = c;
    __syncthreads();
#pragma unroll
    for (int off = 1; off < SCAN_B; off <<= 1) {
        int v = (t >= off) ? sm[t - off] : 0;
        __syncthreads();
        sm[t] += v;
        __syncthreads();
    }
    if (i < N) g_row[i] = sm[t] - c;            // exclusive, block-local
    if (t == SCAN_B - 1) g_aux[blockIdx.x] = sm[t];
}

// ---------- K3b: scan the block sums (one block) ----------
__global__ void k_scanB(int nblk) {
    __shared__ int sm[NBLKMAX];
    int t = threadIdx.x;
    int c = (t < nblk) ? g_aux[t] : 0;
    if (t < nblk) sm[t] = c;
    __syncthreads();
    for (int off = 1; off < nblk; off <<= 1) {
        int v = (t >= off && t < nblk) ? sm[t - off] : 0;
        __syncthreads();
        if (t < nblk) sm[t] += v;
        __syncthreads();
    }
    if (t < nblk) g_aux[t] = sm[t] - c;         // exclusive
}

// ---------- K3c: add block offsets, snapshot write cursors ----------
__global__ void k_scanC(int N, int ET) {
    int i = blockIdx.x * blockDim.x + threadIdx.x;
    if (i >= N) return;
    int r = g_row[i] + g_aux[i >> 10];
    g_row[i]  = r;
    g_woff[i] = r;
    if (i == 0) g_row[N] = ET;
}

// ---------- K4: scatter src ids into dst-sorted order (incl. self-loops) ----------
__global__ void k_scatter(const int* __restrict__ ei, int E, int ET) {
    int e = blockIdx.x * blockDim.x + threadIdx.x;
    if (e >= ET) return;
    int s, d;
    if (e < E) { s = __ldg(&ei[e]); d = __ldg(&ei[E + e]); }
    else       { s = d = e - E; }
    int pos = atomicAdd(&g_woff[d], 1);
    g_src[pos] = s;
}

// ---------- K5: layer-1 aggregation (warp/node) fused with ELU + W2 + layer-2 logits ----------
__global__ void k_agg1(const float* __restrict__ b1,
                       const float* __restrict__ W2,
                       const float* __restrict__ a_src2,
                       const float* __restrict__ a_dst2,
                       int N) {
    int warp = (blockIdx.x * blockDim.x + threadIdx.x) >> 5;
    if (warp >= N) return;
    int lane = threadIdx.x & 31;
    int head = lane >> 4;
    int n = warp;

    float ad = g_ald1[n * 2 + head];
    int beg = g_row[n], end = g_row[n + 1];

    float acc = 0.f, sumex = 0.f;
    int k = beg;
    for (; k + 2 <= end; k += 2) {
        int s0 = g_src[k];
        int s1 = g_src[k + 1];
        float as0 = g_als1[s0 * 2 + head];
        float as1 = g_als1[s1 * 2 + head];
        float h0 = g_h1[(size_t)s0 * F1 + lane];
        float h1 = g_h1[(size_t)s1 * F1 + lane];
        float e0 = as0 + ad; e0 = (e0 > 0.f) ? e0 : 0.2f * e0;
        float e1 = as1 + ad; e1 = (e1 > 0.f) ? e1 : 0.2f * e1;
        float x0 = __expf(e0), x1 = __expf(e1);
        acc += x0 * h0 + x1 * h1;
        sumex += x0 + x1;
    }
    if (k < end) {
        int s0 = g_src[k];
        float as0 = g_als1[s0 * 2 + head];
        float h0 = g_h1[(size_t)s0 * F1 + lane];
        float e0 = as0 + ad; e0 = (e0 > 0.f) ? e0 : 0.2f * e0;
        float x0 = __expf(e0);
        acc += x0 * h0;
        sumex += x0;
    }

    // normalize + bias + ELU
    float o = acc / sumex + __ldg(&b1[lane]);
    o = (o > 0.f) ? o : expm1f(o);

    // layer-2 transform: 32 -> 2 via warp reduction
    float h2a = o * __ldg(&W2[lane * 2]);
    float h2b = o * __ldg(&W2[lane * 2 + 1]);
#pragma unroll
    for (int off = 16; off; off >>= 1) {
        h2a += __shfl_xor_sync(0xffffffffu, h2a, off);
        h2b += __shfl_xor_sync(0xffffffffu, h2b, off);
    }
    if (lane == 0) {
        g_h2[n * 2]     = h2a;
        g_h2[n * 2 + 1] = h2b;
        g_als2[n] = h2a * __ldg(&a_src2[0]) + h2b * __ldg(&a_src2[1]);
        g_ald2[n] = h2a * __ldg(&a_dst2[0]) + h2b * __ldg(&a_dst2[1]);
    }
}

// ---------- K6: layer-2 aggregation (thread/node) fused with output ----------
__global__ void k_agg2(const float* __restrict__ b2,
                       float* __restrict__ out, int N) {
    int n = blockIdx.x * blockDim.x + threadIdx.x;
    if (n >= N) return;
    float ad = g_ald2[n];
    int beg = g_row[n], end = g_row[n + 1];

    float a0 = 0.f, a1 = 0.f, sum = 0.f;
    int k = beg;
    for (; k + 2 <= end; k += 2) {
        int s0 = g_src[k];
        int s1 = g_src[k + 1];
        float v0 = g_als2[s0] + ad;
        float v1 = g_als2[s1] + ad;
        float2 h0 = *(const float2*)&g_h2[s0 * 2];
        float2 h1 = *(const float2*)&g_h2[s1 * 2];
        v0 = (v0 > 0.f) ? v0 : 0.2f * v0;
        v1 = (v1 > 0.f) ? v1 : 0.2f * v1;
        float x0 = __expf(v0), x1 = __expf(v1);
        a0 += x0 * h0.x + x1 * h1.x;
        a1 += x0 * h0.y + x1 * h1.y;
        sum += x0 + x1;
    }
    if (k < end) {
        int s0 = g_src[k];
        float v0 = g_als2[s0] + ad;
        float2 h0 = *(const float2*)&g_h2[s0 * 2];
        v0 = (v0 > 0.f) ? v0 : 0.2f * v0;
        float x0 = __expf(v0);
        a0 += x0 * h0.x;
        a1 += x0 * h0.y;
        sum += x0;
    }
    float inv = 1.f / sum;
    out[n * 2]     = a0 * inv + __ldg(&b2[0]);
    out[n * 2 + 1] = a1 * inv + __ldg(&b2[1]);
}

extern "C" void kernel_launch(void* const* d_in, const int* in_sizes, int n_in,
                              void* d_out, int out_size) {
    const float* x   = (const float*)d_in[0];
    const int*   ei  = (const int*)d_in[1];
    const float* W1  = (const float*)d_in[2];
    const float* as1 = (const float*)d_in[3];
    const float* ad1 = (const float*)d_in[4];
    const float* b1  = (const float*)d_in[5];
    const float* W2  = (const float*)d_in[6];
    const float* as2 = (const float*)d_in[7];
    const float* ad2 = (const float*)d_in[8];
    const float* b2  = (const float*)d_in[9];
    float* out = (float*)d_out;

    int N  = in_sizes[0] / 4;
    int E  = in_sizes[1] / 2;
    int ET = E + N;
    int nblk = (N + SCAN_B - 1) / SCAN_B;

    const int TB = 256;
    k_node1 <<<(N  + TB - 1) / TB, TB>>>((const float4*)x, W1, as1, ad1, N);
    k_hist  <<<(E  + TB - 1) / TB, TB>>>(ei, E);
    k_scanA <<<nblk, SCAN_B>>>(N);
    k_scanB <<<1, 128>>>(nblk);
    k_scanC <<<(N  + TB - 1) / TB, TB>>>(N, ET);
    k_scatter<<<(ET + TB - 1) / TB, TB>>>(ei, E, ET);
    k_agg1  <<<(N * 32 + TB - 1) / TB, TB>>>(b1, W2, as2, ad2, N);
    k_agg2  <<<(N  + TB - 1) / TB, TB>>>(b2, out, N);
}

// round 4
// speedup vs baseline: 1.6521x; 1.0740x over previous
#include <cuda_runtime.h>

#define NMAX 100000
#define EMAX 1700000
#define F1 32            // heads1 * ch1 = 2*16
#define SCAN_B 1024
#define NBLKMAX ((NMAX + SCAN_B - 1) / SCAN_B)   // 98

// ---------- scratch ----------
__device__ __align__(16) float g_h1  [NMAX * F1];
__device__ __align__(16) float g_als1[NMAX * 2];
__device__ __align__(16) float g_ald1[NMAX * 2];
__device__ __align__(16) float4 g_n2 [NMAX];     // {als2, h2a, h2b, ald2}
__device__ int g_cnt [NMAX];        // edge histogram (left zeroed by scanA)
__device__ int g_row [NMAX + 1];    // CSR row starts
__device__ int g_woff[NMAX];        // scatter cursors
__device__ int g_aux [NBLKMAX];     // per-block scan sums
__device__ int g_src [EMAX];        // dst-sorted src ids

// ---------- K1: fused node transform + logits + dst histogram ----------
__global__ void k_fused1(const float4* __restrict__ x,
                         const float*  __restrict__ W1,
                         const float*  __restrict__ a_src,
                         const float*  __restrict__ a_dst,
                         const int*    __restrict__ ei,
                         int N, int E) {
    int i = blockIdx.x * blockDim.x + threadIdx.x;
    if (i < N) {
        float4 xv = x[i];
        float als0 = 0.f, als1 = 0.f, ald0 = 0.f, ald1 = 0.f;
        float* hp = &g_h1[(size_t)i * F1];
#pragma unroll
        for (int j = 0; j < F1; j++) {
            float h = xv.x * __ldg(&W1[j])
                    + xv.y * __ldg(&W1[32 + j])
                    + xv.z * __ldg(&W1[64 + j])
                    + xv.w * __ldg(&W1[96 + j]);
            hp[j] = h;
            float as = __ldg(&a_src[j]);
            float ad = __ldg(&a_dst[j]);
            if (j < 16) { als0 += h * as; ald0 += h * ad; }
            else        { als1 += h * as; ald1 += h * ad; }
        }
        g_als1[i * 2]     = als0;  g_als1[i * 2 + 1] = als1;
        g_ald1[i * 2]     = ald0;  g_ald1[i * 2 + 1] = ald1;
    }
    if (i < E) {
        atomicAdd(&g_cnt[__ldg(&ei[E + i])], 1);
    }
}

// ---------- K2: per-block exclusive scan of (cnt+1); re-zero cnt ----------
__global__ void k_scanA(int N) {
    __shared__ int sm[SCAN_B];
    int t = threadIdx.x;
    int i = blockIdx.x * SCAN_B + t;
    int c = 0;
    if (i < N) { c = g_cnt[i] + 1; g_cnt[i] = 0; }   // +1 self-loop; reset for next call
    sm[t] = c;
    __syncthreads();
#pragma unroll
    for (int off = 1; off < SCAN_B; off <<= 1) {
        int v = (t >= off) ? sm[t - off] : 0;
        __syncthreads();
        sm[t] += v;
        __syncthreads();
    }
    if (i < N) g_row[i] = sm[t] - c;            // exclusive, block-local
    if (t == SCAN_B - 1) g_aux[blockIdx.x] = sm[t];
}

// ---------- K3: add block offsets (each block reduces aux itself) ----------
__global__ void k_scanBC(int N, int ET, int nblk) {
    __shared__ int s_off;
    int t = threadIdx.x;
    if (t < 32) {
        int acc = 0;
        for (int j = t; j < nblk; j += 32)
            if (j < (int)blockIdx.x) acc += g_aux[j];
#pragma unroll
        for (int off = 16; off; off >>= 1)
            acc += __shfl_xor_sync(0xffffffffu, acc, off);
        if (t == 0) s_off = acc;
    }
    __syncthreads();
    int off = s_off;
    int i = blockIdx.x * SCAN_B + t;
    if (i < N) {
        int r = g_row[i] + off;
        g_row[i]  = r;
        g_woff[i] = r;
    }
    if (i == 0) g_row[N] = ET;
}

// ---------- K4: scatter src ids into dst-sorted order (incl. self-loops) ----------
__global__ void k_scatter(const int* __restrict__ ei, int E, int ET) {
    int e = blockIdx.x * blockDim.x + threadIdx.x;
    if (e >= ET) return;
    int s, d;
    if (e < E) { s = __ldg(&ei[e]); d = __ldg(&ei[E + e]); }
    else       { s = d = e - E; }
    int pos = atomicAdd(&g_woff[d], 1);
    g_src[pos] = s;
}

// ---------- K5: layer-1 aggregation (warp/node, lane-batched edges)
//             fused with ELU + W2 + layer-2 logits ----------
__global__ void k_agg1(const float* __restrict__ b1,
                       const float* __restrict__ W2,
                       const float* __restrict__ a_src2,
                       const float* __restrict__ a_dst2,
                       int N) {
    int warp = (blockIdx.x * blockDim.x + threadIdx.x) >> 5;
    if (warp >= N) return;
    int lane = threadIdx.x & 31;
    int n = warp;

    float ad0 = g_ald1[n * 2];
    float ad1 = g_ald1[n * 2 + 1];
    int beg = g_row[n], end = g_row[n + 1];

    float acc = 0.f, sum0 = 0.f, sum1 = 0.f;
    for (int base = beg; base < end; base += 32) {
        int m = end - base; if (m > 32) m = 32;
        int s = 0; float ex0 = 0.f, ex1 = 0.f;
        if (lane < m) {
            s = __ldg(&g_src[base + lane]);
            float2 as = *(const float2*)&g_als1[s * 2];
            float e0 = as.x + ad0; e0 = (e0 > 0.f) ? e0 : 0.2f * e0;
            float e1 = as.y + ad1; e1 = (e1 > 0.f) ? e1 : 0.2f * e1;
            ex0 = __expf(e0);
            ex1 = __expf(e1);
        }
        sum0 += ex0;
        sum1 += ex1;
#pragma unroll 4
        for (int j = 0; j < m; j++) {
            int   sj = __shfl_sync(0xffffffffu, s,   j);
            float x0 = __shfl_sync(0xffffffffu, ex0, j);
            float x1 = __shfl_sync(0xffffffffu, ex1, j);
            float h  = __ldg(&g_h1[(size_t)sj * F1 + lane]);
            acc += ((lane < 16) ? x0 : x1) * h;
        }
    }
#pragma unroll
    for (int off = 16; off; off >>= 1) {
        sum0 += __shfl_xor_sync(0xffffffffu, sum0, off);
        sum1 += __shfl_xor_sync(0xffffffffu, sum1, off);
    }
    float sum = (lane < 16) ? sum0 : sum1;

    // normalize + bias + ELU
    float o = acc / sum + __ldg(&b1[lane]);
    o = (o > 0.f) ? o : expm1f(o);

    // layer-2 transform: 32 -> 2 via warp reduction
    float h2a = o * __ldg(&W2[lane * 2]);
    float h2b = o * __ldg(&W2[lane * 2 + 1]);
#pragma unroll
    for (int off = 16; off; off >>= 1) {
        h2a += __shfl_xor_sync(0xffffffffu, h2a, off);
        h2b += __shfl_xor_sync(0xffffffffu, h2b, off);
    }
    if (lane == 0) {
        float als2 = h2a * __ldg(&a_src2[0]) + h2b * __ldg(&a_src2[1]);
        float ald2 = h2a * __ldg(&a_dst2[0]) + h2b * __ldg(&a_dst2[1]);
        g_n2[n] = make_float4(als2, h2a, h2b, ald2);
    }
}

// ---------- K6: layer-2 aggregation (thread/node) fused with output ----------
__global__ void k_agg2(const float* __restrict__ b2,
                       float* __restrict__ out, int N) {
    int n = blockIdx.x * blockDim.x + threadIdx.x;
    if (n >= N) return;
    float ad = g_n2[n].w;
    int beg = g_row[n], end = g_row[n + 1];

    float a0 = 0.f, a1 = 0.f, sum = 0.f;
#pragma unroll 4
    for (int k = beg; k < end; k++) {
        int s = __ldg(&g_src[k]);
        float4 v = __ldg(&g_n2[s]);
        float e = v.x + ad; e = (e > 0.f) ? e : 0.2f * e;
        float ex = __expf(e);
        a0  += ex * v.y;
        a1  += ex * v.z;
        sum += ex;
    }
    float inv = 1.f / sum;
    out[n * 2]     = a0 * inv + __ldg(&b2[0]);
    out[n * 2 + 1] = a1 * inv + __ldg(&b2[1]);
}

extern "C" void kernel_launch(void* const* d_in, const int* in_sizes, int n_in,
                              void* d_out, int out_size) {
    const float* x   = (const float*)d_in[0];
    const int*   ei  = (const int*)d_in[1];
    const float* W1  = (const float*)d_in[2];
    const float* as1 = (const float*)d_in[3];
    const float* ad1 = (const float*)d_in[4];
    const float* b1  = (const float*)d_in[5];
    const float* W2  = (const float*)d_in[6];
    const float* as2 = (const float*)d_in[7];
    const float* ad2 = (const float*)d_in[8];
    const float* b2  = (const float*)d_in[9];
    float* out = (float*)d_out;

    int N  = in_sizes[0] / 4;
    int E  = in_sizes[1] / 2;
    int ET = E + N;
    int nblk = (N + SCAN_B - 1) / SCAN_B;
    int big = (E > N) ? E : N;

    const int TB = 256;
    k_fused1<<<(big + TB - 1) / TB, TB>>>((const float4*)x, W1, as1, ad1, ei, N, E);
    k_scanA <<<nblk, SCAN_B>>>(N);
    k_scanBC<<<nblk, SCAN_B>>>(N, ET, nblk);
    k_scatter<<<(ET + TB - 1) / TB, TB>>>(ei, E, ET);
    k_agg1  <<<(N * 32 + TB - 1) / TB, TB>>>(b1, W2, as2, ad2, N);
    k_agg2  <<<(N + TB - 1) / TB, TB>>>(b2, out, N);
}